// round 12
// baseline (speedup 1.0000x reference)
#include <cuda_runtime.h>
#include <cstdint>
#include <cstddef>

typedef unsigned long long ull;

#define BB 64
#define TT 1024
#define DD 256
#define UU 256
#define MM (BB*TT)          // 65536 rows for the input projection

// ---- scan: 512 threads = 2 k-halves x 256 u; TWO batch rows per CTA ----
// per-thread k range = 128 values = 64 packed pairs:
//   40 pairs register-resident, 24 pairs streamed from SMEM (shared by both rows)
#define PREG 40
#define PSTR 24            // streamed pairs per thread -> ws = 2*24*256*8 = 96 KB

// ---------------- packed f32x2 helpers ----------------
__device__ __forceinline__ ull fma2(ull a, ull b, ull c){
    ull d;
    asm("fma.rn.f32x2 %0, %1, %2, %3;" : "=l"(d) : "l"(a), "l"(b), "l"(c));
    return d;
}
__device__ __forceinline__ float2 unpack2(ull a){
    float2 r;
    asm("mov.b64 {%0, %1}, %2;" : "=f"(r.x), "=f"(r.y) : "l"(a));
    return r;
}
__device__ __forceinline__ ull pack2(float lo, float hi){
    ull p;
    asm("mov.b64 %0, {%1, %2};" : "=l"(p) : "f"(lo), "f"(hi));
    return p;
}
__device__ __forceinline__ ull wload(const float* W, int k, int u){
    return pack2(W[(size_t)k*UU + u], W[(size_t)(k+1)*UU + u]);
}

// fast tanh: branchless, 2 MUFU ops; clamp keeps exp finite for any input
__device__ __forceinline__ float fast_tanh(float x){
    float xc = fminf(fmaxf(x, -15.f), 15.f);
    float e  = __expf(2.f*xc);
    return __fdividef(e - 1.f, e + 1.f);
}

// ---------------- input projection GEMM: 2 CTAs/SM for staging/compute overlap ----
#define GR 16   // rows per block (halved so 2 CTAs fit per SM)

__device__ __forceinline__ void gemm_chunk(const float* xs, int cc, const ull* w, ull* acc){
    #pragma unroll
    for (int r = 0; r < GR; r++){
        const ulonglong2* xr = reinterpret_cast<const ulonglong2*>(xs + r*UU) + cc*4;
        #pragma unroll
        for (int j = 0; j < 4; j++){
            ulonglong2 xx = xr[j];
            acc[r] = fma2(xx.x, w[2*j],   acc[r]);
            acc[r] = fma2(xx.y, w[2*j+1], acc[r]);
        }
    }
}

__global__ void __launch_bounds__(256,2) gemm_kernel(const float* __restrict__ X,
                                                     const float* __restrict__ Wxh,
                                                     const float* __restrict__ bh,
                                                     float* __restrict__ out){
    __shared__ __align__(16) float xs[GR*UU];        // 16 KB x-tile
    const int u    = threadIdx.x;
    const int row0 = blockIdx.x * GR;

    {
        const float4* Xv = reinterpret_cast<const float4*>(X + (size_t)row0*UU);
        float4* sv = reinterpret_cast<float4*>(xs);
        #pragma unroll
        for (int i = 0; i < (GR*UU/4)/256; i++)
            sv[threadIdx.x + i*256] = Xv[threadIdx.x + i*256];
    }
    float bias = bh[u];
    __syncthreads();

    ull acc[GR];
    #pragma unroll
    for (int r = 0; r < GR; r++) acc[r] = 0ULL;

    ull wcur[8], wnxt[8];
    #pragma unroll
    for (int j = 0; j < 8; j++) wcur[j] = wload(Wxh, 2*j, u);

    #pragma unroll 1
    for (int c = 0; c < 16; c += 2){
        #pragma unroll
        for (int j = 0; j < 8; j++) wnxt[j] = wload(Wxh, 2*((c+1)*8 + j), u);
        gemm_chunk(xs, c, wcur, acc);
        if (c + 2 < 16){
            #pragma unroll
            for (int j = 0; j < 8; j++) wcur[j] = wload(Wxh, 2*((c+2)*8 + j), u);
        }
        gemm_chunk(xs, c+1, wnxt, acc);
    }

    #pragma unroll
    for (int r = 0; r < GR; r++){
        float2 v = unpack2(acc[r]);
        out[(size_t)(row0 + r)*UU + u] = v.x + v.y + bias;   // xW pre-activation
    }
}

// ---------------- sequential scan: 2 batch rows per CTA, 512 threads, 2-way k-split --
// thread (u = t&255, kh = t>>8) covers k in [kh*128, kh*128+128) for column u,
// for BOTH rows. Weights (regs + streamed SMEM) are shared across the two rows:
// the 96 KB/step crossbar traffic is amortized 2x, and the 4 independent
// accumulator chains + 2 hv streams fill the latency-exposure gap.
extern __shared__ ull ws[];   // [2*PSTR][UU] packed pairs (96 KB)

__global__ void __launch_bounds__(512,1) scan_kernel(const float* __restrict__ Whh,
                                                     float* __restrict__ out){
    __shared__ __align__(16) float hbuf[2][2][UU];   // [parity][row][u]
    __shared__ float redbuf[2][UU];                  // [row][u]
    const int t  = threadIdx.x;
    const int u  = t & 255;
    const int kh = t >> 8;                 // 0/1
    const int kbase = kh*128;
    const int b0 = blockIdx.x*2;

    // register-resident pairs: k = kbase + 2j, j in [0, PREG)
    ull w[PREG];
    #pragma unroll
    for (int j = 0; j < PREG; j++) w[j] = wload(Whh, kbase + 2*j, u);

    // streamed pairs: k = kbase + 2*PREG + 2i, i in [0, PSTR)
    #pragma unroll
    for (int i = 0; i < PSTR; i++)
        ws[(kh*PSTR + i)*UU + u] = wload(Whh, kbase + 2*PREG + 2*i, u);

    if (t < UU){
        hbuf[0][0][t] = 0.f; hbuf[0][1][t] = 0.f;
        hbuf[1][0][t] = 0.f; hbuf[1][1][t] = 0.f;
    }
    __syncthreads();

    float* row0 = out + ((size_t)b0    *TT)*UU + u;  // kh==0 threads own outputs
    float* row1 = out + ((size_t)(b0+1)*TT)*UU + u;

    int p = 0;
    #pragma unroll 1
    for (int tt = 0; tt < TT; tt++){
        float xw0 = 0.f, xw1 = 0.f;
        if (kh == 0){ xw0 = row0[0]; xw1 = row1[0]; }   // L2-resident pre-activations

        const ulonglong2* hv0 = reinterpret_cast<const ulonglong2*>(&hbuf[p][0][kbase]);
        const ulonglong2* hv1 = reinterpret_cast<const ulonglong2*>(&hbuf[p][1][kbase]);

        ull a0r0 = 0ULL, a1r0 = 0ULL, a0r1 = 0ULL, a1r1 = 0ULL;

        // register-weight part: weights reused across both rows (4 indep chains)
        #pragma unroll
        for (int i = 0; i < PREG/2; i++){
            ulonglong2 h0 = hv0[i];
            ulonglong2 h1 = hv1[i];
            a0r0 = fma2(h0.x, w[2*i],   a0r0);
            a0r1 = fma2(h1.x, w[2*i],   a0r1);
            a1r0 = fma2(h0.y, w[2*i+1], a1r0);
            a1r1 = fma2(h1.y, w[2*i+1], a1r1);
        }
        // streamed part: each ws value loaded ONCE, used for both rows
        #pragma unroll
        for (int i = 0; i < PSTR/2; i++){
            ull wa = ws[(kh*PSTR + 2*i)*UU + u];
            ull wb = ws[(kh*PSTR + 2*i+1)*UU + u];
            ulonglong2 h0 = hv0[PREG/2 + i];
            ulonglong2 h1 = hv1[PREG/2 + i];
            a0r0 = fma2(h0.x, wa, a0r0);
            a0r1 = fma2(h1.x, wa, a0r1);
            a1r0 = fma2(h0.y, wb, a1r0);
            a1r1 = fma2(h1.y, wb, a1r1);
        }

        float2 v0 = unpack2(a0r0), v1 = unpack2(a1r0);
        float part0 = (v0.x + v0.y) + (v1.x + v1.y);
        float2 v2 = unpack2(a0r1), v3 = unpack2(a1r1);
        float part1 = (v2.x + v2.y) + (v3.x + v3.y);

        if (kh == 1){ redbuf[0][u] = part0; redbuf[1][u] = part1; }
        __syncthreads();                         // partials ready

        if (kh == 0){
            float h0 = fast_tanh(part0 + redbuf[0][u] + xw0);
            float h1 = fast_tanh(part1 + redbuf[1][u] + xw1);
            hbuf[p^1][0][u] = h0;
            hbuf[p^1][1][u] = h1;
            row0[0] = h0;  row0 += UU;
            row1[0] = h1;  row1 += UU;
        }
        __syncthreads();                         // next h visible to all
        p ^= 1;
    }
}

// ---------------- launch ----------------
extern "C" void kernel_launch(void* const* d_in, const int* in_sizes, int n_in,
                              void* d_out, int out_size){
    int idx_inputs = -1, idx_b = -1;
    int widx[2] = {-1, -1}; int nw = 0;
    for (int i = 0; i < n_in; i++){
        long long sz = in_sizes[i];
        if      (sz == (long long)MM*DD || sz == (long long)MM*DD*4) idx_inputs = i;
        else if (sz == UU || sz == UU*4)                             idx_b = i;
        else if (nw < 2)                                             widx[nw++] = i;
    }

    const float *X, *bh, *Wxh, *Whh;
    if (idx_inputs >= 0 && idx_b >= 0 && nw == 2){
        X  = (const float*)d_in[idx_inputs];
        bh = (const float*)d_in[idx_b];
        if (idx_inputs < widx[0]){
            Wxh = (const float*)d_in[widx[0]];
            Whh = (const float*)d_in[widx[1]];
        } else {
            Whh = (const float*)d_in[widx[0]];
            Wxh = (const float*)d_in[widx[1]];
        }
    } else {
        X   = (const float*)d_in[0];
        Wxh = (const float*)d_in[1];
        Whh = (const float*)d_in[2];
        bh  = (const float*)d_in[3];
    }
    float* out = (float*)d_out;                 // [64,1024,256] fp32

    const int WS_BYTES = 2*PSTR*UU*8;           // 96 KB
    cudaFuncSetAttribute(scan_kernel, cudaFuncAttributeMaxDynamicSharedMemorySize, WS_BYTES);

    gemm_kernel<<<MM/GR, 256>>>(X, Wxh, bh, out);
    scan_kernel<<<BB/2, 512, WS_BYTES>>>(Whh, out);   // 32 CTAs, 2 rows each
}

// round 13
// speedup vs baseline: 1.2856x; 1.2856x over previous
#include <cuda_runtime.h>
#include <cstdint>
#include <cstddef>

typedef unsigned long long ull;

#define BB 64
#define TT 1024
#define DD 256
#define UU 256
#define MM (BB*TT)          // 65536 rows for the input projection

// ---- scan: 512 threads, pair-split: u = t>>1 (256 u), kh = t&1 (k-half) ----
// per-thread k range = 128 values = 64 packed pairs:
#define PREG 44            // pairs in registers (88 regs)
#define PSTR 20            // pairs streamed from SMEM -> 512*20*8 = 80 KB/step

// ---------------- packed f32x2 helpers ----------------
__device__ __forceinline__ ull fma2(ull a, ull b, ull c){
    ull d;
    asm("fma.rn.f32x2 %0, %1, %2, %3;" : "=l"(d) : "l"(a), "l"(b), "l"(c));
    return d;
}
__device__ __forceinline__ float2 unpack2(ull a){
    float2 r;
    asm("mov.b64 {%0, %1}, %2;" : "=f"(r.x), "=f"(r.y) : "l"(a));
    return r;
}
__device__ __forceinline__ ull pack2(float lo, float hi){
    ull p;
    asm("mov.b64 %0, {%1, %2};" : "=l"(p) : "f"(lo), "f"(hi));
    return p;
}
__device__ __forceinline__ ull wload(const float* W, int k, int u){
    return pack2(W[(size_t)k*UU + u], W[(size_t)(k+1)*UU + u]);
}

// fast tanh: branchless, 2 MUFU ops; clamp keeps exp finite for any input
__device__ __forceinline__ float fast_tanh(float x){
    float xc = fminf(fmaxf(x, -15.f), 15.f);
    float e  = __expf(2.f*xc);
    return __fdividef(e - 1.f, e + 1.f);
}

// ---------------- input projection GEMM: 2 CTAs/SM (proven ~equal to GR32) ----
#define GR 16   // rows per block

__device__ __forceinline__ void gemm_chunk(const float* xs, int cc, const ull* w, ull* acc){
    #pragma unroll
    for (int r = 0; r < GR; r++){
        const ulonglong2* xr = reinterpret_cast<const ulonglong2*>(xs + r*UU) + cc*4;
        #pragma unroll
        for (int j = 0; j < 4; j++){
            ulonglong2 xx = xr[j];
            acc[r] = fma2(xx.x, w[2*j],   acc[r]);
            acc[r] = fma2(xx.y, w[2*j+1], acc[r]);
        }
    }
}

__global__ void __launch_bounds__(256,2) gemm_kernel(const float* __restrict__ X,
                                                     const float* __restrict__ Wxh,
                                                     const float* __restrict__ bh,
                                                     float* __restrict__ out){
    __shared__ __align__(16) float xs[GR*UU];        // 16 KB x-tile
    const int u    = threadIdx.x;
    const int row0 = blockIdx.x * GR;

    {
        const float4* Xv = reinterpret_cast<const float4*>(X + (size_t)row0*UU);
        float4* sv = reinterpret_cast<float4*>(xs);
        #pragma unroll
        for (int i = 0; i < (GR*UU/4)/256; i++)
            sv[threadIdx.x + i*256] = Xv[threadIdx.x + i*256];
    }
    float bias = bh[u];
    __syncthreads();

    ull acc[GR];
    #pragma unroll
    for (int r = 0; r < GR; r++) acc[r] = 0ULL;

    ull wcur[8], wnxt[8];
    #pragma unroll
    for (int j = 0; j < 8; j++) wcur[j] = wload(Wxh, 2*j, u);

    #pragma unroll 1
    for (int c = 0; c < 16; c += 2){
        #pragma unroll
        for (int j = 0; j < 8; j++) wnxt[j] = wload(Wxh, 2*((c+1)*8 + j), u);
        gemm_chunk(xs, c, wcur, acc);
        if (c + 2 < 16){
            #pragma unroll
            for (int j = 0; j < 8; j++) wcur[j] = wload(Wxh, 2*((c+2)*8 + j), u);
        }
        gemm_chunk(xs, c+1, wnxt, acc);
    }

    #pragma unroll
    for (int r = 0; r < GR; r++){
        float2 v = unpack2(acc[r]);
        out[(size_t)(row0 + r)*UU + u] = v.x + v.y + bias;   // xW pre-activation
    }
}

// ---------------- sequential scan: 1 CTA/row, 512 threads, pair k-split ----
// Thread pair (t even/odd) shares u = t>>1; kh = t&1 picks k in [kh*128, kh*128+128).
// Partials combine via shfl_xor (no redbuf, ONE __syncthreads per step).
// ws laid out [pair_idx][tid] -> consecutive lanes, conflict-free LDS.
// hbuf halves padded to 132 floats so the two kh broadcast groups use
// different banks.
extern __shared__ ull ws[];   // PSTR*512 packed pairs (80 KB)

#define HPAD 132

__global__ void __launch_bounds__(512,1) scan_kernel(const float* __restrict__ Whh,
                                                     float* __restrict__ out){
    __shared__ __align__(16) float hbuf[2][2][HPAD];  // [parity][khalf][idx]
    const int t  = threadIdx.x;
    const int u  = t >> 1;
    const int kh = t & 1;
    const int kbase = kh*128;
    const int b  = blockIdx.x;

    // register-resident pairs: k = kbase + 2j, j in [0, PREG)
    ull w[PREG];
    #pragma unroll
    for (int j = 0; j < PREG; j++) w[j] = wload(Whh, kbase + 2*j, u);

    // streamed pairs, [i][tid] layout: k = kbase + 2*PREG + 2i
    #pragma unroll
    for (int i = 0; i < PSTR; i++)
        ws[i*512 + t] = wload(Whh, kbase + 2*PREG + 2*i, u);

    {   // zero both parities of hbuf
        float* hb = &hbuf[0][0][0];
        for (int i = t; i < 2*2*HPAD; i += 512) hb[i] = 0.f;
    }
    __syncthreads();

    float* row = out + ((size_t)b*TT)*UU + u;   // kh==0 thread owns this column

    int p = 0;
    #pragma unroll 1
    for (int tt = 0; tt < TT; tt++){
        float xw = (kh == 0) ? row[0] : 0.f;    // pre-activation (L2)

        const ulonglong2* hv = reinterpret_cast<const ulonglong2*>(&hbuf[p][kh][0]);

        ull a0 = 0ULL, a1 = 0ULL;
        // register-weight part: 44 FMA2 (22 hv entries = 88 k)
        #pragma unroll
        for (int i = 0; i < PREG/2; i++){
            ulonglong2 hh = hv[i];               // broadcast LDS.128
            a0 = fma2(hh.x, w[2*i],   a0);
            a1 = fma2(hh.y, w[2*i+1], a1);
        }
        // streamed part: 20 FMA2 (10 hv entries = 40 k)
        #pragma unroll
        for (int i = 0; i < PSTR/2; i++){
            ull wa = ws[(2*i)*512 + t];
            ull wb = ws[(2*i+1)*512 + t];
            ulonglong2 hh = hv[PREG/2 + i];
            a0 = fma2(hh.x, wa, a0);
            a1 = fma2(hh.y, wb, a1);
        }

        float2 v0 = unpack2(a0), v1 = unpack2(a1);
        float part = (v0.x + v0.y) + (v1.x + v1.y);

        // combine the pair's k-half partials in-warp (no smem, no extra BAR)
        float other = __shfl_xor_sync(0xFFFFFFFFu, part, 1);

        if (kh == 0){
            float h = fast_tanh(part + other + xw);
            hbuf[p^1][u >> 7][u & 127] = h;
            row[0] = h;
        }
        row += UU;
        __syncthreads();                         // h visible to all for next step
        p ^= 1;
    }
}

// ---------------- launch ----------------
extern "C" void kernel_launch(void* const* d_in, const int* in_sizes, int n_in,
                              void* d_out, int out_size){
    int idx_inputs = -1, idx_b = -1;
    int widx[2] = {-1, -1}; int nw = 0;
    for (int i = 0; i < n_in; i++){
        long long sz = in_sizes[i];
        if      (sz == (long long)MM*DD || sz == (long long)MM*DD*4) idx_inputs = i;
        else if (sz == UU || sz == UU*4)                             idx_b = i;
        else if (nw < 2)                                             widx[nw++] = i;
    }

    const float *X, *bh, *Wxh, *Whh;
    if (idx_inputs >= 0 && idx_b >= 0 && nw == 2){
        X  = (const float*)d_in[idx_inputs];
        bh = (const float*)d_in[idx_b];
        if (idx_inputs < widx[0]){
            Wxh = (const float*)d_in[widx[0]];
            Whh = (const float*)d_in[widx[1]];
        } else {
            Whh = (const float*)d_in[widx[0]];
            Wxh = (const float*)d_in[widx[1]];
        }
    } else {
        X   = (const float*)d_in[0];
        Wxh = (const float*)d_in[1];
        Whh = (const float*)d_in[2];
        bh  = (const float*)d_in[3];
    }
    float* out = (float*)d_out;                 // [64,1024,256] fp32

    const int WS_BYTES = PSTR*512*8;            // 80 KB
    cudaFuncSetAttribute(scan_kernel, cudaFuncAttributeMaxDynamicSharedMemorySize, WS_BYTES);

    gemm_kernel<<<MM/GR, 256>>>(X, Wxh, bh, out);
    scan_kernel<<<BB, 512, WS_BYTES>>>(Whh, out);
}

// round 14
// speedup vs baseline: 1.7587x; 1.3680x over previous
#include <cuda_runtime.h>
#include <cstdint>
#include <cstddef>

typedef unsigned long long ull;

#define BB 64
#define TT 1024
#define DD 256
#define UU 256
#define MM (BB*TT)

// scan (R10-proven): 512 threads = 2 k-halves x 256 u, warp-uniform kh
#define PREG 40            // pairs in regs (80 regs)
#define PSTR 24            // pairs streamed -> ws = 2*24*256*8 = 96 KB
#define WS_BYTES (2*PSTR*UU*8)

// producer->consumer flags: gemm chunk (b, c) covers t in [c*32, c*32+32)
__device__ int g_flag[BB][TT/32];    // 8 KB static (pitfalls.md-endorsed scratch)

// ---------------- packed f32x2 helpers ----------------
__device__ __forceinline__ ull fma2(ull a, ull b, ull c){
    ull d;
    asm("fma.rn.f32x2 %0, %1, %2, %3;" : "=l"(d) : "l"(a), "l"(b), "l"(c));
    return d;
}
__device__ __forceinline__ float2 unpack2(ull a){
    float2 r;
    asm("mov.b64 {%0, %1}, %2;" : "=f"(r.x), "=f"(r.y) : "l"(a));
    return r;
}
__device__ __forceinline__ ull pack2(float lo, float hi){
    ull p;
    asm("mov.b64 %0, {%1, %2};" : "=l"(p) : "f"(lo), "f"(hi));
    return p;
}
__device__ __forceinline__ ull wload(const float* W, int k, int u){
    return pack2(W[(size_t)k*UU + u], W[(size_t)(k+1)*UU + u]);
}
__device__ __forceinline__ float fast_tanh(float x){
    float xc = fminf(fmaxf(x, -15.f), 15.f);
    float e  = __expf(2.f*xc);
    return __fdividef(e - 1.f, e + 1.f);
}

// ---------------- flag clear (runs before the fused kernel each replay) ----
__global__ void clear_flags(){
    int* f = &g_flag[0][0];
    #pragma unroll
    for (int i = 0; i < 4; i++) f[threadIdx.x + i*512] = 0;
}

// ---------------- fused kernel: blocks 0..63 scan, 64..2111 gemm ----------
extern __shared__ ull ws[];   // scan: 96 KB weight stream; gemm: 32 KB x-tile

__global__ void __launch_bounds__(512,1)
fused_kernel(const float* __restrict__ X,
             const float* __restrict__ Wxh,
             const float* __restrict__ Whh,
             const float* __restrict__ bh,
             float* __restrict__ out){
    __shared__ __align__(16) float hbuf[2][UU];
    __shared__ float redbuf[UU];

    const int t = threadIdx.x;

    if (blockIdx.x >= BB){
        // ================= GEMM role: 32 rows of xW = X@Wxh + b =================
        const int g  = blockIdx.x - BB;
        const int b  = g & 63;
        const int c  = g >> 6;                  // chunk index: rows b*1024 + c*32 ..+32
        const int row0 = b*TT + c*32;
        const int u  = t & 255;
        const int rh = t >> 8;                  // row half: 0 -> rows 0..15, 1 -> 16..31

        float* xs = (float*)ws;                 // 32 KB tile
        {
            const float4* Xv = reinterpret_cast<const float4*>(X + (size_t)row0*UU);
            float4* sv = reinterpret_cast<float4*>(xs);
            #pragma unroll
            for (int i = 0; i < 4; i++) sv[t + i*512] = Xv[t + i*512];
        }
        float bias = bh[u];
        __syncthreads();

        ull acc[16];
        #pragma unroll
        for (int r = 0; r < 16; r++) acc[r] = 0ULL;

        const float* xrows = xs + rh*16*UU;

        ull wcur[8], wnxt[8];
        #pragma unroll
        for (int j = 0; j < 8; j++) wcur[j] = wload(Wxh, 2*j, u);

        #pragma unroll 1
        for (int cc = 0; cc < 16; cc += 2){
            #pragma unroll
            for (int j = 0; j < 8; j++) wnxt[j] = wload(Wxh, 2*((cc+1)*8 + j), u);
            #pragma unroll
            for (int r = 0; r < 16; r++){
                const ulonglong2* xr = reinterpret_cast<const ulonglong2*>(xrows + r*UU) + cc*4;
                #pragma unroll
                for (int j = 0; j < 4; j++){
                    ulonglong2 xx = xr[j];
                    acc[r] = fma2(xx.x, wcur[2*j],   acc[r]);
                    acc[r] = fma2(xx.y, wcur[2*j+1], acc[r]);
                }
            }
            if (cc + 2 < 16){
                #pragma unroll
                for (int j = 0; j < 8; j++) wcur[j] = wload(Wxh, 2*((cc+2)*8 + j), u);
            }
            #pragma unroll
            for (int r = 0; r < 16; r++){
                const ulonglong2* xr = reinterpret_cast<const ulonglong2*>(xrows + r*UU) + (cc+1)*4;
                #pragma unroll
                for (int j = 0; j < 4; j++){
                    ulonglong2 xx = xr[j];
                    acc[r] = fma2(xx.x, wnxt[2*j],   acc[r]);
                    acc[r] = fma2(xx.y, wnxt[2*j+1], acc[r]);
                }
            }
        }

        #pragma unroll
        for (int r = 0; r < 16; r++){
            float2 v = unpack2(acc[r]);
            out[(size_t)(row0 + rh*16 + r)*UU + u] = v.x + v.y + bias;
        }

        __threadfence();                        // data before flag
        __syncthreads();                        // all threads' fences done
        if (t == 0) *((volatile int*)&g_flag[b][c]) = 1;
        return;
    }

    // ================= SCAN role (R10 layout, verbatim + chunk poll) ==========
    const int u  = t & 255;
    const int kh = t >> 8;                      // warp-uniform
    const int b  = blockIdx.x;
    const int kbase = kh*128;

    ull w[PREG];
    #pragma unroll
    for (int j = 0; j < PREG; j++) w[j] = wload(Whh, kbase + 2*j, u);

    #pragma unroll
    for (int i = 0; i < PSTR; i++)
        ws[(kh*PSTR + i)*UU + u] = wload(Whh, kbase + 2*PREG + 2*i, u);

    if (t < UU){ hbuf[0][t] = 0.f; hbuf[1][t] = 0.f; }
    __syncthreads();

    float* row = out + ((size_t)b*TT)*UU + u;

    int p = 0;
    #pragma unroll 1
    for (int tt = 0; tt < TT; tt++){
        if ((tt & 31) == 0){
            if (t == 0){
                volatile int* f = &g_flag[b][tt >> 5];
                while (*f == 0) { }
                __threadfence();                // acquire: producer's data visible
            }
            __syncthreads();
        }

        float xw = (kh == 0) ? row[0] : 0.f;    // pre-activation (L2/DRAM), hoisted

        const ulonglong2* hv = reinterpret_cast<const ulonglong2*>(&hbuf[p][kbase]);

        ull a0 = 0ULL, a1 = 0ULL;
        #pragma unroll
        for (int i = 0; i < PREG/2; i++){
            ulonglong2 hh = hv[i];              // broadcast LDS.128
            a0 = fma2(hh.x, w[2*i],   a0);
            a1 = fma2(hh.y, w[2*i+1], a1);
        }
        #pragma unroll
        for (int i = 0; i < PSTR/2; i++){
            ulonglong2 hh = hv[PREG/2 + i];
            a0 = fma2(hh.x, ws[(kh*PSTR + 2*i)*UU + u],   a0);
            a1 = fma2(hh.y, ws[(kh*PSTR + 2*i+1)*UU + u], a1);
        }

        float2 v0 = unpack2(a0), v1 = unpack2(a1);
        float part = (v0.x + v0.y) + (v1.x + v1.y);

        if (kh == 1) redbuf[u] = part;
        __syncthreads();

        if (kh == 0){
            float h = fast_tanh(part + redbuf[u] + xw);
            hbuf[p^1][u] = h;
            row[0] = h;
            row += UU;
        }
        __syncthreads();
        p ^= 1;
    }
}

// ---------------- launch ----------------
extern "C" void kernel_launch(void* const* d_in, const int* in_sizes, int n_in,
                              void* d_out, int out_size){
    int idx_inputs = -1, idx_b = -1;
    int widx[2] = {-1, -1}; int nw = 0;
    for (int i = 0; i < n_in; i++){
        long long sz = in_sizes[i];
        if      (sz == (long long)MM*DD || sz == (long long)MM*DD*4) idx_inputs = i;
        else if (sz == UU || sz == UU*4)                             idx_b = i;
        else if (nw < 2)                                             widx[nw++] = i;
    }

    const float *X, *bh, *Wxh, *Whh;
    if (idx_inputs >= 0 && idx_b >= 0 && nw == 2){
        X  = (const float*)d_in[idx_inputs];
        bh = (const float*)d_in[idx_b];
        if (idx_inputs < widx[0]){
            Wxh = (const float*)d_in[widx[0]];
            Whh = (const float*)d_in[widx[1]];
        } else {
            Whh = (const float*)d_in[widx[0]];
            Wxh = (const float*)d_in[widx[1]];
        }
    } else {
        X   = (const float*)d_in[0];
        Wxh = (const float*)d_in[1];
        Whh = (const float*)d_in[2];
        bh  = (const float*)d_in[3];
    }
    float* out = (float*)d_out;                 // [64,1024,256] fp32

    cudaFuncSetAttribute(fused_kernel, cudaFuncAttributeMaxDynamicSharedMemorySize, WS_BYTES);

    clear_flags<<<1, 512>>>();
    fused_kernel<<<BB + BB*(TT/32)/1, 512, WS_BYTES>>>(X, Wxh, Whh, bh, out);
    // grid = 64 scan CTAs + 2048 gemm CTAs (32 rows each) = 2112
}

// round 15
// speedup vs baseline: 1.8393x; 1.0458x over previous
#include <cuda_runtime.h>
#include <cstdint>
#include <cstddef>

typedef unsigned long long ull;

#define BB 64
#define TT 1024
#define DD 256
#define UU 256
#define MM (BB*TT)

// scan: 512 threads = 2 k-halves x 256 u, warp-uniform kh (R10-proven layout)
#define PREG 44            // pairs in regs (88 regs)
#define PSTR 20            // pairs streamed; stored as ulonglong2 (2 pairs/entry)
#define WS_BYTES (2*(PSTR/2)*UU*16)   // 80 KB

// producer->consumer flags: gemm chunk (b, c) covers t in [c*32, c*32+32)
__device__ int g_flag[BB][TT/32];    // 8 KB static

// ---------------- packed f32x2 helpers ----------------
__device__ __forceinline__ ull fma2(ull a, ull b, ull c){
    ull d;
    asm("fma.rn.f32x2 %0, %1, %2, %3;" : "=l"(d) : "l"(a), "l"(b), "l"(c));
    return d;
}
__device__ __forceinline__ float2 unpack2(ull a){
    float2 r;
    asm("mov.b64 {%0, %1}, %2;" : "=f"(r.x), "=f"(r.y) : "l"(a));
    return r;
}
__device__ __forceinline__ ull pack2(float lo, float hi){
    ull p;
    asm("mov.b64 %0, {%1, %2};" : "=l"(p) : "f"(lo), "f"(hi));
    return p;
}
__device__ __forceinline__ ull wload(const float* W, int k, int u){
    return pack2(W[(size_t)k*UU + u], W[(size_t)(k+1)*UU + u]);
}
__device__ __forceinline__ float fast_tanh(float x){
    float xc = fminf(fmaxf(x, -15.f), 15.f);
    float e  = __expf(2.f*xc);
    return __fdividef(e - 1.f, e + 1.f);
}
__device__ __forceinline__ void bar_named(int id, int cnt){
    asm volatile("bar.sync %0, %1;" :: "r"(id), "r"(cnt) : "memory");
}

// ---------------- flag clear (runs before the fused kernel each replay) ----
__global__ void clear_flags(){
    int* f = &g_flag[0][0];
    #pragma unroll
    for (int i = 0; i < 4; i++) f[threadIdx.x + i*512] = 0;
}

// ---------------- fused kernel: blocks 0..63 scan, 64..2111 gemm ----------
extern __shared__ ull ws[];   // scan: 80 KB weight stream; gemm: 32 KB x-tile

__global__ void __launch_bounds__(512,1)
fused_kernel(const float* __restrict__ X,
             const float* __restrict__ Wxh,
             const float* __restrict__ Whh,
             const float* __restrict__ bh,
             float* __restrict__ out){
    __shared__ __align__(16) float hbuf[2][UU];
    __shared__ float redbuf[UU];

    const int t = threadIdx.x;

    if (blockIdx.x >= BB){
        // ================= GEMM role: 32 rows of xW = X@Wxh + b =================
        const int g  = blockIdx.x - BB;
        const int b  = g & 63;
        const int c  = g >> 6;
        const int row0 = b*TT + c*32;
        const int u  = t & 255;
        const int rh = t >> 8;

        float* xs = (float*)ws;                 // 32 KB tile
        {
            const float4* Xv = reinterpret_cast<const float4*>(X + (size_t)row0*UU);
            float4* sv = reinterpret_cast<float4*>(xs);
            #pragma unroll
            for (int i = 0; i < 4; i++) sv[t + i*512] = Xv[t + i*512];
        }
        float bias = bh[u];
        __syncthreads();

        ull acc[16];
        #pragma unroll
        for (int r = 0; r < 16; r++) acc[r] = 0ULL;

        const float* xrows = xs + rh*16*UU;

        ull wcur[8], wnxt[8];
        #pragma unroll
        for (int j = 0; j < 8; j++) wcur[j] = wload(Wxh, 2*j, u);

        #pragma unroll 1
        for (int cc = 0; cc < 16; cc += 2){
            #pragma unroll
            for (int j = 0; j < 8; j++) wnxt[j] = wload(Wxh, 2*((cc+1)*8 + j), u);
            #pragma unroll
            for (int r = 0; r < 16; r++){
                const ulonglong2* xr = reinterpret_cast<const ulonglong2*>(xrows + r*UU) + cc*4;
                #pragma unroll
                for (int j = 0; j < 4; j++){
                    ulonglong2 xx = xr[j];
                    acc[r] = fma2(xx.x, wcur[2*j],   acc[r]);
                    acc[r] = fma2(xx.y, wcur[2*j+1], acc[r]);
                }
            }
            if (cc + 2 < 16){
                #pragma unroll
                for (int j = 0; j < 8; j++) wcur[j] = wload(Wxh, 2*((cc+2)*8 + j), u);
            }
            #pragma unroll
            for (int r = 0; r < 16; r++){
                const ulonglong2* xr = reinterpret_cast<const ulonglong2*>(xrows + r*UU) + (cc+1)*4;
                #pragma unroll
                for (int j = 0; j < 4; j++){
                    ulonglong2 xx = xr[j];
                    acc[r] = fma2(xx.x, wnxt[2*j],   acc[r]);
                    acc[r] = fma2(xx.y, wnxt[2*j+1], acc[r]);
                }
            }
        }

        #pragma unroll
        for (int r = 0; r < 16; r++){
            float2 v = unpack2(acc[r]);
            out[(size_t)(row0 + rh*16 + r)*UU + u] = v.x + v.y + bias;
        }

        __threadfence();
        __syncthreads();
        if (t == 0) *((volatile int*)&g_flag[b][c]) = 1;
        return;
    }

    // ================= SCAN role =============================================
    const int u   = t & 255;
    const int kh  = t >> 8;                     // warp-uniform
    const int wid = t >> 5;
    const int b   = blockIdx.x;
    const int kbase = kh*128;
    const int pair_bar = 1 + (wid & 7);         // warp w <-> warp w+8

    // register-resident pairs: k = kbase + 2j, j in [0, PREG)
    ull w[PREG];
    #pragma unroll
    for (int j = 0; j < PREG; j++) w[j] = wload(Whh, kbase + 2*j, u);

    // streamed pairs as ulonglong2 (pairs 2i and 2i+1 together):
    // entry i covers k = kbase + 2*PREG + 4i .. +3
    ulonglong2* ws2 = reinterpret_cast<ulonglong2*>(ws);
    #pragma unroll
    for (int i = 0; i < PSTR/2; i++){
        ull wa = wload(Whh, kbase + 2*PREG + 4*i,     u);
        ull wb = wload(Whh, kbase + 2*PREG + 4*i + 2, u);
        ws2[(kh*(PSTR/2) + i)*UU + u] = make_ulonglong2(wa, wb);
    }

    if (t < UU){ hbuf[0][t] = 0.f; hbuf[1][t] = 0.f; }
    __syncthreads();

    float* row = out + ((size_t)b*TT)*UU + u;

    int p = 0;
    #pragma unroll 1
    for (int tt = 0; tt < TT; tt++){
        if ((tt & 31) == 0){
            if (t == 0){
                volatile int* f = &g_flag[b][tt >> 5];
                while (*f == 0) { }
                __threadfence();
            }
            __syncthreads();
        }

        float xw = (kh == 0) ? row[0] : 0.f;

        const ulonglong2* hv = reinterpret_cast<const ulonglong2*>(&hbuf[p][kbase]);

        ull a0 = 0ULL, a1 = 0ULL;
        // register part: 44 FMA2 over hv[0..21]
        #pragma unroll
        for (int i = 0; i < PREG/2; i++){
            ulonglong2 hh = hv[i];              // broadcast LDS.128
            a0 = fma2(hh.x, w[2*i],   a0);
            a1 = fma2(hh.y, w[2*i+1], a1);
        }
        // streamed part: 20 FMA2 over hv[22..31], weights via LDS.128
        #pragma unroll
        for (int i = 0; i < PSTR/2; i++){
            ulonglong2 wp = ws2[(kh*(PSTR/2) + i)*UU + u];
            ulonglong2 hh = hv[PREG/2 + i];
            a0 = fma2(hh.x, wp.x, a0);
            a1 = fma2(hh.y, wp.y, a1);
        }

        float2 v0 = unpack2(a0), v1 = unpack2(a1);
        float part = (v0.x + v0.y) + (v1.x + v1.y);

        if (kh == 1) redbuf[u] = part;
        bar_named(pair_bar, 64);                // pairwise reduce sync (warps w, w+8)

        if (kh == 0){
            float h = fast_tanh(part + redbuf[u] + xw);
            hbuf[p^1][u] = h;
            row[0] = h;
            row += UU;
        }
        __syncthreads();                        // h visible to all for next step
        p ^= 1;
    }
}

// ---------------- launch ----------------
extern "C" void kernel_launch(void* const* d_in, const int* in_sizes, int n_in,
                              void* d_out, int out_size){
    int idx_inputs = -1, idx_b = -1;
    int widx[2] = {-1, -1}; int nw = 0;
    for (int i = 0; i < n_in; i++){
        long long sz = in_sizes[i];
        if      (sz == (long long)MM*DD || sz == (long long)MM*DD*4) idx_inputs = i;
        else if (sz == UU || sz == UU*4)                             idx_b = i;
        else if (nw < 2)                                             widx[nw++] = i;
    }

    const float *X, *bh, *Wxh, *Whh;
    if (idx_inputs >= 0 && idx_b >= 0 && nw == 2){
        X  = (const float*)d_in[idx_inputs];
        bh = (const float*)d_in[idx_b];
        if (idx_inputs < widx[0]){
            Wxh = (const float*)d_in[widx[0]];
            Whh = (const float*)d_in[widx[1]];
        } else {
            Whh = (const float*)d_in[widx[0]];
            Wxh = (const float*)d_in[widx[1]];
        }
    } else {
        X   = (const float*)d_in[0];
        Wxh = (const float*)d_in[1];
        Whh = (const float*)d_in[2];
        bh  = (const float*)d_in[3];
    }
    float* out = (float*)d_out;                 // [64,1024,256] fp32

    cudaFuncSetAttribute(fused_kernel, cudaFuncAttributeMaxDynamicSharedMemorySize, WS_BYTES);

    clear_flags<<<1, 512>>>();
    fused_kernel<<<BB + BB*(TT/32), 512, WS_BYTES>>>(X, Wxh, Whh, bh, out);
}